// round 15
// baseline (speedup 1.0000x reference)
#include <cuda_runtime.h>
#include <cuda_bf16.h>
#include <cstdint>

#define SRC_LEN 512
#define BATCH   64
#define HIDDEN  1024
#define EMBED   1024
#define NBLK    128          // scan CTAs = 32 j-tiles x 4 b-tiles

// Scratch (static __device__ arrays: allowed, no runtime allocation)
__device__ float    g_xproj[SRC_LEN * BATCH * HIDDEN];   // [t][b][j]
__device__ unsigned g_hx[2][BATCH * HIDDEN];             // h packed (bf16 hi | lo<<16)
__device__ unsigned g_bar;

__device__ __forceinline__ uint32_t smem_u32(const void* p) {
    uint32_t a;
    asm("{ .reg .u64 t; cvta.to.shared.u64 t, %1; cvt.u32.u64 %0, t; }" : "=r"(a) : "l"(p));
    return a;
}
__device__ __forceinline__ unsigned prmt(unsigned a, unsigned b, unsigned s) {
    unsigned d; asm("prmt.b32 %0, %1, %2, %3;" : "=r"(d) : "r"(a), "r"(b), "r"(s)); return d;
}

// ---- warp-level bf16 MMA primitives (sm_80+, safe on bare sm_103) ---------
#define LDSM_X4(r, a) \
    asm volatile("ldmatrix.sync.aligned.m8n8.x4.shared.b16 {%0,%1,%2,%3}, [%4];" \
        : "=r"((r)[0]), "=r"((r)[1]), "=r"((r)[2]), "=r"((r)[3]) : "r"(a))

__device__ __forceinline__ void mma16816(float* c, const unsigned* a,
                                         unsigned b0, unsigned b1) {
    asm volatile(
        "mma.sync.aligned.m16n8k16.row.col.f32.bf16.bf16.f32 "
        "{%0,%1,%2,%3}, {%4,%5,%6,%7}, {%8,%9}, {%0,%1,%2,%3};"
        : "+f"(c[0]), "+f"(c[1]), "+f"(c[2]), "+f"(c[3])
        : "r"(a[0]), "r"(a[1]), "r"(a[2]), "r"(a[3]), "r"(b0), "r"(b1));
}

__device__ __forceinline__ unsigned bf2u(__nv_bfloat162 h) {
    unsigned u; __builtin_memcpy(&u, &h, 4); return u;
}
// 8 fp32 -> 8 bf16 hi + 8 bf16 lo (split)
__device__ __forceinline__ void cvt8(float4 a, float4 b, uint4& hi, uint4& lo) {
    __nv_bfloat162 h0 = __float22bfloat162_rn(make_float2(a.x, a.y));
    __nv_bfloat162 h1 = __float22bfloat162_rn(make_float2(a.z, a.w));
    __nv_bfloat162 h2 = __float22bfloat162_rn(make_float2(b.x, b.y));
    __nv_bfloat162 h3 = __float22bfloat162_rn(make_float2(b.z, b.w));
    float2 f0 = __bfloat1622float2(h0), f1 = __bfloat1622float2(h1);
    float2 f2 = __bfloat1622float2(h2), f3 = __bfloat1622float2(h3);
    __nv_bfloat162 l0 = __float22bfloat162_rn(make_float2(a.x - f0.x, a.y - f0.y));
    __nv_bfloat162 l1 = __float22bfloat162_rn(make_float2(a.z - f1.x, a.w - f1.y));
    __nv_bfloat162 l2 = __float22bfloat162_rn(make_float2(b.x - f2.x, b.y - f2.y));
    __nv_bfloat162 l3 = __float22bfloat162_rn(make_float2(b.z - f3.x, b.w - f3.y));
    hi = make_uint4(bf2u(h0), bf2u(h1), bf2u(h2), bf2u(h3));
    lo = make_uint4(bf2u(l0), bf2u(l1), bf2u(l2), bf2u(l3));
}
// 4 fp32 -> 4 bf16 hi + lo (for W prologue)
__device__ __forceinline__ void cvt4(float4 a, uint2& hi, uint2& lo) {
    __nv_bfloat162 h0 = __float22bfloat162_rn(make_float2(a.x, a.y));
    __nv_bfloat162 h1 = __float22bfloat162_rn(make_float2(a.z, a.w));
    float2 f0 = __bfloat1622float2(h0), f1 = __bfloat1622float2(h1);
    __nv_bfloat162 l0 = __float22bfloat162_rn(make_float2(a.x - f0.x, a.y - f0.y));
    __nv_bfloat162 l1 = __float22bfloat162_rn(make_float2(a.z - f1.x, a.w - f1.y));
    hi = make_uint2(bf2u(h0), bf2u(h1));
    lo = make_uint2(bf2u(l0), bf2u(l1));
}
// fp32 -> packed (bf16 hi | bf16 lo << 16)
__device__ __forceinline__ unsigned packsplit(float v) {
    __nv_bfloat16 hb = __float2bfloat16_rn(v);
    float hf = __bfloat162float(hb);
    __nv_bfloat16 lb = __float2bfloat16_rn(v - hf);
    unsigned short hu, lu;
    __builtin_memcpy(&hu, &hb, 2); __builtin_memcpy(&lu, &lb, 2);
    return (unsigned)hu | ((unsigned)lu << 16);
}

// ---------------------------------------------------------------------------
__global__ void init_kernel() {
    unsigned i = blockIdx.x * blockDim.x + threadIdx.x;
    if (i == 0) g_bar = 0u;
    if (i < HIDDEN * BATCH) g_hx[0][i] = 0u;
}
// ncu-steering no-op: capture (4th launch) lands on the scan kernel.
__global__ void probe_kernel() { }

// ---------------------------------------------------------------------------
// Stage 1 (warp MMA, unchanged from R12 WIN): epilogue [t][b][j].
// ---------------------------------------------------------------------------
#define XROWB 80           // bytes per SMEM row (32 data + 8 pad bf16)

__global__ __launch_bounds__(256, 2) void xproj_kernel(
    const int*   __restrict__ src,
    const float* __restrict__ emb,
    const float* __restrict__ Wxh,
    const float* __restrict__ bxh)
{
    __shared__ __align__(16) unsigned char smAH[128 * XROWB];
    __shared__ __align__(16) unsigned char smAL[128 * XROWB];
    __shared__ __align__(16) unsigned char smBH[128 * XROWB];
    __shared__ __align__(16) unsigned char smBL[128 * XROWB];

    const int tid = threadIdx.x;
    const int j0 = blockIdx.x * 128;
    const int t0 = blockIdx.y * 2;

    const int ra = tid >> 1;
    const int kh = (tid & 1) * 16;
    const int bb = ra & 63, tl0 = ra >> 6;
    const int er = __ldg(src + bb * SRC_LEN + t0 + tl0);
    const float* arow = emb + (size_t)er * EMBED + kh;
    const float* brow = Wxh + (size_t)(j0 + ra) * EMBED + kh;
    unsigned char* pAH = smAH + ra * XROWB + kh * 2;
    unsigned char* pAL = smAL + ra * XROWB + kh * 2;
    unsigned char* pBH = smBH + ra * XROWB + kh * 2;
    unsigned char* pBL = smBL + ra * XROWB + kh * 2;

    const int l = tid & 31, w = tid >> 5;
    const int rowA = 16 * w + (l & 7) + (l & 8);
    const int kA   = (l >> 4) * 8;
    const uint32_t aAH = smem_u32(smAH) + rowA * XROWB + kA * 2;
    const uint32_t aAL = smem_u32(smAL) + rowA * XROWB + kA * 2;
    const int rowB = (l & 7) + ((l >= 16) ? 8 : 0);
    const int kB   = (l & 8) ? 8 : 0;
    const uint32_t aBH = smem_u32(smBH) + rowB * XROWB + kB * 2;
    const uint32_t aBL = smem_u32(smBL) + rowB * XROWB + kB * 2;

    float acc[16][4];
#pragma unroll
    for (int n = 0; n < 16; ++n) { acc[n][0]=0.f; acc[n][1]=0.f; acc[n][2]=0.f; acc[n][3]=0.f; }

    for (int c = 0; c < EMBED / 32; ++c) {
        const int k0 = c * 32;
        float4 va0 = __ldg((const float4*)(arow + k0));
        float4 va1 = __ldg((const float4*)(arow + k0 + 4));
        float4 va2 = __ldg((const float4*)(arow + k0 + 8));
        float4 va3 = __ldg((const float4*)(arow + k0 + 12));
        float4 vb0 = __ldg((const float4*)(brow + k0));
        float4 vb1 = __ldg((const float4*)(brow + k0 + 4));
        float4 vb2 = __ldg((const float4*)(brow + k0 + 8));
        float4 vb3 = __ldg((const float4*)(brow + k0 + 12));
        __syncthreads();
        uint4 h, lo;
        cvt8(va0, va1, h, lo); *(uint4*)pAH = h; *(uint4*)pAL = lo;
        cvt8(va2, va3, h, lo); *(uint4*)(pAH + 16) = h; *(uint4*)(pAL + 16) = lo;
        cvt8(vb0, vb1, h, lo); *(uint4*)pBH = h; *(uint4*)pBL = lo;
        cvt8(vb2, vb3, h, lo); *(uint4*)(pBH + 16) = h; *(uint4*)(pBL + 16) = lo;
        __syncthreads();

#pragma unroll
        for (int kk = 0; kk < 2; ++kk) {
            unsigned ah[4], al[4];
            LDSM_X4(ah, aAH + kk * 32);
            LDSM_X4(al, aAL + kk * 32);
#pragma unroll
            for (int g = 0; g < 8; ++g) {
                unsigned bh[4], bl[4];
                LDSM_X4(bh, aBH + g * 16 * XROWB + kk * 32);
                LDSM_X4(bl, aBL + g * 16 * XROWB + kk * 32);
                mma16816(acc[2*g],   ah, bh[0], bh[1]);
                mma16816(acc[2*g],   ah, bl[0], bl[1]);
                mma16816(acc[2*g],   al, bh[0], bh[1]);
                mma16816(acc[2*g+1], ah, bh[2], bh[3]);
                mma16816(acc[2*g+1], ah, bl[2], bl[3]);
                mma16816(acc[2*g+1], al, bh[2], bh[3]);
            }
        }
    }

    // epilogue -> g_xproj[t][b][j], float2 stores (j even)
    const int r0 = 16 * w + (l >> 2);
    const int tl = r0 >> 6, b0 = r0 & 63;
    float* base0 = g_xproj + ((size_t)(t0 + tl) * BATCH + b0) * HIDDEN;
    float* base1 = g_xproj + ((size_t)(t0 + tl) * BATCH + b0 + 8) * HIDDEN;
#pragma unroll
    for (int nt = 0; nt < 16; ++nt) {
        const int j = j0 + nt * 8 + (l & 3) * 2;
        const float bj0 = __ldg(bxh + j), bj1 = __ldg(bxh + j + 1);
        *(float2*)(base0 + j) = make_float2(acc[nt][0] + bj0, acc[nt][1] + bj1);
        *(float2*)(base1 + j) = make_float2(acc[nt][2] + bj0, acc[nt][3] + bj1);
    }
}

// ---------------------------------------------------------------------------
// Stage 2 v4 (warp MMA): h stored PRE-SPLIT (bf16 hi|lo packed u32) ->
// staging is uint4 load + PRMT (no cvt). Grid barrier via red.release +
// ld.acquire (no MEMBAR, no ATOMG round-trip). Otherwise as R12 WIN.
// ---------------------------------------------------------------------------
#define KROWB   2064        // bytes per 1024-bf16 row (+8 pad)
#define OFF_WH  0
#define OFF_WL  66048
#define OFF_AH  132096
#define OFF_AL  165120
#define OFF_RED 198144
#define SCAN_SMEM 218624

__global__ __launch_bounds__(256) void rnn_scan_kernel(
    const float* __restrict__ Whh, float* __restrict__ out)
{
    extern __shared__ __align__(16) unsigned char dynsm[];
    const uint32_t sbase = smem_u32(dynsm);
    float* red = (float*)(dynsm + OFF_RED);

    const int tid = threadIdx.x;
    const int l = tid & 31, w = tid >> 5;
    const int jt = blockIdx.x >> 2, bt = blockIdx.x & 3;

    // ---- W prologue: rows jt*32..+31 fp32 -> bf16 hi/lo SMEM [j][k] ----
    {
        const int r = tid >> 3, kq = tid & 7;
        const float* wr = Whh + (size_t)(jt * 32 + r) * HIDDEN;
        unsigned char* pH = dynsm + OFF_WH + r * KROWB + kq * 8;
        unsigned char* pL = dynsm + OFF_WL + r * KROWB + kq * 8;
#pragma unroll 8
        for (int i = 0; i < 32; ++i) {
            float4 v = __ldg((const float4*)(wr + kq * 4 + i * 32));
            uint2 h, lo;
            cvt4(v, h, lo);
            *(uint2*)(pH + i * 64) = h;
            *(uint2*)(pL + i * 64) = lo;
        }
    }
    __syncthreads();

    // ---- preload B fragments (W) into registers: warp w = K slice w*128 ----
    const int rowB = (l & 7) + ((l >= 16) ? 8 : 0);
    const int kBy = ((l & 8) ? 16 : 0);
    unsigned bfh[16][4], bfl[16][4];
#pragma unroll
    for (int kk = 0; kk < 8; ++kk) {
#pragma unroll
        for (int g = 0; g < 2; ++g) {
            const uint32_t o = (g * 16 + rowB) * KROWB + w * 256 + kk * 32 + kBy;
            LDSM_X4(bfh[kk * 2 + g], sbase + OFF_WH + o);
            LDSM_X4(bfl[kk * 2 + g], sbase + OFF_WL + o);
        }
    }

    // ---- A-frag lane addresses (XOR-16B swizzle on row bit3) ----
    const int rowA = (l & 7) + (l & 8);
    const int kAy = (l >> 4) * 16;
    const uint32_t aAH = sbase + OFF_AH + rowA * KROWB
                       + (kAy ^ ((rowA & 8) << 1)) + w * 256;
    const uint32_t aAL = aAH + (OFF_AL - OFF_AH);

    // ---- staging ids ----
    const int sb_ = tid >> 4, skq = tid & 15;
    const int sgoff = (bt * 16 + sb_) * HIDDEN;
    const uint32_t sAH = OFF_AH + sb_ * KROWB + ((skq * 8) ^ ((sb_ & 8) << 1));
    const uint32_t sAL = sAH + (OFF_AL - OFF_AH);

    // ---- reduce ids ----
    const int jj = tid & 31, brow = tid >> 5;

    unsigned expected = 0;
    int cur = 0;
    float lastv0 = 0.f, lastv1 = 0.f;

    for (int t = 0; t < SRC_LEN; ++t) {
        const size_t xb = (size_t)t * (BATCH * HIDDEN) + jt * 32 + jj;
        const float xv0 = __ldcg(g_xproj + xb + (size_t)(bt * 16 + brow) * HIDDEN);
        const float xv1 = __ldcg(g_xproj + xb + (size_t)(bt * 16 + brow + 8) * HIDDEN);

        // ---- stage h slice: packed u32 -> PRMT split -> bf16 planes ----
        const unsigned* gh = g_hx[cur] + sgoff;
#pragma unroll
        for (int i = 0; i < 16; ++i) {
            uint4 v = __ldcg((const uint4*)(gh + skq * 4 + i * 64));
            unsigned h01 = prmt(v.x, v.y, 0x5410u);
            unsigned h23 = prmt(v.z, v.w, 0x5410u);
            unsigned l01 = prmt(v.x, v.y, 0x7632u);
            unsigned l23 = prmt(v.z, v.w, 0x7632u);
            *(uint2*)(dynsm + sAH + i * 128) = make_uint2(h01, h23);
            *(uint2*)(dynsm + sAL + i * 128) = make_uint2(l01, l23);
        }
        __syncthreads();

        // ---- MMA: 8 k16 x (4 n-tiles x 3 products) ----
        float acc[4][4];
#pragma unroll
        for (int n = 0; n < 4; ++n) { acc[n][0]=0.f; acc[n][1]=0.f; acc[n][2]=0.f; acc[n][3]=0.f; }
#pragma unroll
        for (int kk = 0; kk < 8; ++kk) {
            unsigned ah[4], al[4];
            LDSM_X4(ah, aAH + kk * 32);
            LDSM_X4(al, aAL + kk * 32);
#pragma unroll
            for (int g = 0; g < 2; ++g) {
                const int ix = kk * 2 + g;
                mma16816(acc[2*g],   ah, bfh[ix][0], bfh[ix][1]);
                mma16816(acc[2*g+1], ah, bfh[ix][2], bfh[ix][3]);
                mma16816(acc[2*g],   ah, bfl[ix][0], bfl[ix][1]);
                mma16816(acc[2*g+1], ah, bfl[ix][2], bfl[ix][3]);
                mma16816(acc[2*g],   al, bfh[ix][0], bfh[ix][1]);
                mma16816(acc[2*g+1], al, bfh[ix][2], bfh[ix][3]);
            }
        }

        // ---- spill partials: red[w][r][c], row stride 40 floats ----
        {
            const int r0 = l >> 2;
            float* rp = red + (w * 16 + r0) * 40;
#pragma unroll
            for (int nt = 0; nt < 4; ++nt) {
                const int c = nt * 8 + (l & 3) * 2;
                *(float2*)(rp + c)          = make_float2(acc[nt][0], acc[nt][1]);
                *(float2*)(rp + 8 * 40 + c) = make_float2(acc[nt][2], acc[nt][3]);
            }
        }
        __syncthreads();

        // ---- reduce 8 warps, + xv, tanh, pack-split, store h_next [b][k] ----
        {
            float s0 = xv0, s1 = xv1;
#pragma unroll
            for (int wq = 0; wq < 8; ++wq) {
                s0 += red[(wq * 16 + brow) * 40 + jj];
                s1 += red[(wq * 16 + brow + 8) * 40 + jj];
            }
            lastv0 = tanhf(s0);
            lastv1 = tanhf(s1);
            unsigned* hn = g_hx[cur ^ 1];
            __stcg(hn + (size_t)(bt * 16 + brow)     * HIDDEN + jt * 32 + jj, packsplit(lastv0));
            __stcg(hn + (size_t)(bt * 16 + brow + 8) * HIDDEN + jt * 32 + jj, packsplit(lastv1));
        }

        // ---- grid barrier: red.release + ld.acquire poll (no MEMBAR) ----
        expected += NBLK;
        __syncthreads();                      // all CTA stores done
        if (tid == 0) {
            asm volatile("red.release.gpu.global.add.u32 [%0], %1;"
                         :: "l"(&g_bar), "r"(1u) : "memory");
            unsigned v;
            do {
                asm volatile("ld.acquire.gpu.global.u32 %0, [%1];"
                             : "=r"(v) : "l"(&g_bar) : "memory");
            } while (v < expected);
        }
        __syncthreads();
        cur ^= 1;
    }
    out[(size_t)(bt * 16 + brow)     * HIDDEN + jt * 32 + jj] = lastv0;
    out[(size_t)(bt * 16 + brow + 8) * HIDDEN + jt * 32 + jj] = lastv1;
}

// ---------------------------------------------------------------------------
extern "C" void kernel_launch(void* const* d_in, const int* in_sizes, int n_in,
                              void* d_out, int out_size)
{
    const int*   src = (const int*)  d_in[0];
    const float* emb = (const float*)d_in[1];
    const float* Wxh = (const float*)d_in[2];
    const float* bxh = (const float*)d_in[3];
    const float* Whh = (const float*)d_in[4];
    float* out = (float*)d_out;

    static int attr_set = 0;
    if (!attr_set) {
        cudaFuncSetAttribute(rnn_scan_kernel,
                             cudaFuncAttributeMaxDynamicSharedMemorySize, SCAN_SMEM);
        attr_set = 1;
    }

    init_kernel<<<256, 256>>>();
    probe_kernel<<<1, 32>>>();       // ncu alignment: capture -> rnn_scan_kernel
    xproj_kernel<<<dim3(8, 256), 256>>>(src, emb, Wxh, bxh);
    rnn_scan_kernel<<<NBLK, 256, SCAN_SMEM>>>(Whh, out);
}

// round 16
// speedup vs baseline: 1.4221x; 1.4221x over previous
#include <cuda_runtime.h>
#include <cuda_bf16.h>
#include <cstdint>

#define SRC_LEN 512
#define BATCH   64
#define HIDDEN  1024
#define EMBED   1024
#define NBLK    128          // scan CTAs = 32 j-tiles x 4 b-tiles

// Scratch (static __device__ arrays: allowed, no runtime allocation)
__device__ float    g_xproj[SRC_LEN * BATCH * HIDDEN];   // [t][b][j]
__device__ unsigned g_hx[2][BATCH * HIDDEN];             // h packed (bf16 hi | lo<<16)
__device__ unsigned g_bar;

__device__ __forceinline__ uint32_t smem_u32(const void* p) {
    uint32_t a;
    asm("{ .reg .u64 t; cvta.to.shared.u64 t, %1; cvt.u32.u64 %0, t; }" : "=r"(a) : "l"(p));
    return a;
}
__device__ __forceinline__ unsigned prmt(unsigned a, unsigned b, unsigned s) {
    unsigned d; asm("prmt.b32 %0, %1, %2, %3;" : "=r"(d) : "r"(a), "r"(b), "r"(s)); return d;
}

// ---- warp-level bf16 MMA primitives (sm_80+, safe on bare sm_103) ---------
#define LDSM_X4(r, a) \
    asm volatile("ldmatrix.sync.aligned.m8n8.x4.shared.b16 {%0,%1,%2,%3}, [%4];" \
        : "=r"((r)[0]), "=r"((r)[1]), "=r"((r)[2]), "=r"((r)[3]) : "r"(a))

__device__ __forceinline__ void mma16816(float* c, const unsigned* a,
                                         unsigned b0, unsigned b1) {
    asm volatile(
        "mma.sync.aligned.m16n8k16.row.col.f32.bf16.bf16.f32 "
        "{%0,%1,%2,%3}, {%4,%5,%6,%7}, {%8,%9}, {%0,%1,%2,%3};"
        : "+f"(c[0]), "+f"(c[1]), "+f"(c[2]), "+f"(c[3])
        : "r"(a[0]), "r"(a[1]), "r"(a[2]), "r"(a[3]), "r"(b0), "r"(b1));
}

__device__ __forceinline__ unsigned bf2u(__nv_bfloat162 h) {
    unsigned u; __builtin_memcpy(&u, &h, 4); return u;
}
// 8 fp32 -> 8 bf16 hi + 8 bf16 lo (split)
__device__ __forceinline__ void cvt8(float4 a, float4 b, uint4& hi, uint4& lo) {
    __nv_bfloat162 h0 = __float22bfloat162_rn(make_float2(a.x, a.y));
    __nv_bfloat162 h1 = __float22bfloat162_rn(make_float2(a.z, a.w));
    __nv_bfloat162 h2 = __float22bfloat162_rn(make_float2(b.x, b.y));
    __nv_bfloat162 h3 = __float22bfloat162_rn(make_float2(b.z, b.w));
    float2 f0 = __bfloat1622float2(h0), f1 = __bfloat1622float2(h1);
    float2 f2 = __bfloat1622float2(h2), f3 = __bfloat1622float2(h3);
    __nv_bfloat162 l0 = __float22bfloat162_rn(make_float2(a.x - f0.x, a.y - f0.y));
    __nv_bfloat162 l1 = __float22bfloat162_rn(make_float2(a.z - f1.x, a.w - f1.y));
    __nv_bfloat162 l2 = __float22bfloat162_rn(make_float2(b.x - f2.x, b.y - f2.y));
    __nv_bfloat162 l3 = __float22bfloat162_rn(make_float2(b.z - f3.x, b.w - f3.y));
    hi = make_uint4(bf2u(h0), bf2u(h1), bf2u(h2), bf2u(h3));
    lo = make_uint4(bf2u(l0), bf2u(l1), bf2u(l2), bf2u(l3));
}
// 4 fp32 -> 4 bf16 hi + lo (for W prologue)
__device__ __forceinline__ void cvt4(float4 a, uint2& hi, uint2& lo) {
    __nv_bfloat162 h0 = __float22bfloat162_rn(make_float2(a.x, a.y));
    __nv_bfloat162 h1 = __float22bfloat162_rn(make_float2(a.z, a.w));
    float2 f0 = __bfloat1622float2(h0), f1 = __bfloat1622float2(h1);
    __nv_bfloat162 l0 = __float22bfloat162_rn(make_float2(a.x - f0.x, a.y - f0.y));
    __nv_bfloat162 l1 = __float22bfloat162_rn(make_float2(a.z - f1.x, a.w - f1.y));
    hi = make_uint2(bf2u(h0), bf2u(h1));
    lo = make_uint2(bf2u(l0), bf2u(l1));
}
// fp32 -> packed (bf16 hi | bf16 lo << 16)
__device__ __forceinline__ unsigned packsplit(float v) {
    __nv_bfloat16 hb = __float2bfloat16_rn(v);
    float hf = __bfloat162float(hb);
    __nv_bfloat16 lb = __float2bfloat16_rn(v - hf);
    unsigned short hu, lu;
    __builtin_memcpy(&hu, &hb, 2); __builtin_memcpy(&lu, &lb, 2);
    return (unsigned)hu | ((unsigned)lu << 16);
}

// ---------------------------------------------------------------------------
__global__ void init_kernel() {
    unsigned i = blockIdx.x * blockDim.x + threadIdx.x;
    if (i == 0) g_bar = 0u;
    if (i < HIDDEN * BATCH) g_hx[0][i] = 0u;
}
// ncu-steering no-op: capture (4th launch) lands on the scan kernel.
__global__ void probe_kernel() { }

// ---------------------------------------------------------------------------
// Stage 1 (warp MMA, unchanged from R12 WIN): epilogue [t][b][j].
// ---------------------------------------------------------------------------
#define XROWB 80           // bytes per SMEM row (32 data + 8 pad bf16)

__global__ __launch_bounds__(256, 2) void xproj_kernel(
    const int*   __restrict__ src,
    const float* __restrict__ emb,
    const float* __restrict__ Wxh,
    const float* __restrict__ bxh)
{
    __shared__ __align__(16) unsigned char smAH[128 * XROWB];
    __shared__ __align__(16) unsigned char smAL[128 * XROWB];
    __shared__ __align__(16) unsigned char smBH[128 * XROWB];
    __shared__ __align__(16) unsigned char smBL[128 * XROWB];

    const int tid = threadIdx.x;
    const int j0 = blockIdx.x * 128;
    const int t0 = blockIdx.y * 2;

    const int ra = tid >> 1;
    const int kh = (tid & 1) * 16;
    const int bb = ra & 63, tl0 = ra >> 6;
    const int er = __ldg(src + bb * SRC_LEN + t0 + tl0);
    const float* arow = emb + (size_t)er * EMBED + kh;
    const float* brow = Wxh + (size_t)(j0 + ra) * EMBED + kh;
    unsigned char* pAH = smAH + ra * XROWB + kh * 2;
    unsigned char* pAL = smAL + ra * XROWB + kh * 2;
    unsigned char* pBH = smBH + ra * XROWB + kh * 2;
    unsigned char* pBL = smBL + ra * XROWB + kh * 2;

    const int l = tid & 31, w = tid >> 5;
    const int rowA = 16 * w + (l & 7) + (l & 8);
    const int kA   = (l >> 4) * 8;
    const uint32_t aAH = smem_u32(smAH) + rowA * XROWB + kA * 2;
    const uint32_t aAL = smem_u32(smAL) + rowA * XROWB + kA * 2;
    const int rowB = (l & 7) + ((l >= 16) ? 8 : 0);
    const int kB   = (l & 8) ? 8 : 0;
    const uint32_t aBH = smem_u32(smBH) + rowB * XROWB + kB * 2;
    const uint32_t aBL = smem_u32(smBL) + rowB * XROWB + kB * 2;

    float acc[16][4];
#pragma unroll
    for (int n = 0; n < 16; ++n) { acc[n][0]=0.f; acc[n][1]=0.f; acc[n][2]=0.f; acc[n][3]=0.f; }

    for (int c = 0; c < EMBED / 32; ++c) {
        const int k0 = c * 32;
        float4 va0 = __ldg((const float4*)(arow + k0));
        float4 va1 = __ldg((const float4*)(arow + k0 + 4));
        float4 va2 = __ldg((const float4*)(arow + k0 + 8));
        float4 va3 = __ldg((const float4*)(arow + k0 + 12));
        float4 vb0 = __ldg((const float4*)(brow + k0));
        float4 vb1 = __ldg((const float4*)(brow + k0 + 4));
        float4 vb2 = __ldg((const float4*)(brow + k0 + 8));
        float4 vb3 = __ldg((const float4*)(brow + k0 + 12));
        __syncthreads();
        uint4 h, lo;
        cvt8(va0, va1, h, lo); *(uint4*)pAH = h; *(uint4*)pAL = lo;
        cvt8(va2, va3, h, lo); *(uint4*)(pAH + 16) = h; *(uint4*)(pAL + 16) = lo;
        cvt8(vb0, vb1, h, lo); *(uint4*)pBH = h; *(uint4*)pBL = lo;
        cvt8(vb2, vb3, h, lo); *(uint4*)(pBH + 16) = h; *(uint4*)(pBL + 16) = lo;
        __syncthreads();

#pragma unroll
        for (int kk = 0; kk < 2; ++kk) {
            unsigned ah[4], al[4];
            LDSM_X4(ah, aAH + kk * 32);
            LDSM_X4(al, aAL + kk * 32);
#pragma unroll
            for (int g = 0; g < 8; ++g) {
                unsigned bh[4], bl[4];
                LDSM_X4(bh, aBH + g * 16 * XROWB + kk * 32);
                LDSM_X4(bl, aBL + g * 16 * XROWB + kk * 32);
                mma16816(acc[2*g],   ah, bh[0], bh[1]);
                mma16816(acc[2*g],   ah, bl[0], bl[1]);
                mma16816(acc[2*g],   al, bh[0], bh[1]);
                mma16816(acc[2*g+1], ah, bh[2], bh[3]);
                mma16816(acc[2*g+1], ah, bl[2], bl[3]);
                mma16816(acc[2*g+1], al, bh[2], bh[3]);
            }
        }
    }

    // epilogue -> g_xproj[t][b][j], float2 stores (j even)
    const int r0 = 16 * w + (l >> 2);
    const int tl = r0 >> 6, b0 = r0 & 63;
    float* base0 = g_xproj + ((size_t)(t0 + tl) * BATCH + b0) * HIDDEN;
    float* base1 = g_xproj + ((size_t)(t0 + tl) * BATCH + b0 + 8) * HIDDEN;
#pragma unroll
    for (int nt = 0; nt < 16; ++nt) {
        const int j = j0 + nt * 8 + (l & 3) * 2;
        const float bj0 = __ldg(bxh + j), bj1 = __ldg(bxh + j + 1);
        *(float2*)(base0 + j) = make_float2(acc[nt][0] + bj0, acc[nt][1] + bj1);
        *(float2*)(base1 + j) = make_float2(acc[nt][2] + bj0, acc[nt][3] + bj1);
    }
}

// ---------------------------------------------------------------------------
// Stage 2 v5: packed-h staging (uint4 + PRMT, no cvt) KEPT from R15;
// grid barrier REVERTED to R12's proven threadfence + atomicAdd + volatile
// spin (the release/acquire poll is the suspected R15 regression).
// ---------------------------------------------------------------------------
#define KROWB   2064        // bytes per 1024-bf16 row (+8 pad)
#define OFF_WH  0
#define OFF_WL  66048
#define OFF_AH  132096
#define OFF_AL  165120
#define OFF_RED 198144
#define SCAN_SMEM 218624

__global__ __launch_bounds__(256) void rnn_scan_kernel(
    const float* __restrict__ Whh, float* __restrict__ out)
{
    extern __shared__ __align__(16) unsigned char dynsm[];
    const uint32_t sbase = smem_u32(dynsm);
    float* red = (float*)(dynsm + OFF_RED);

    const int tid = threadIdx.x;
    const int l = tid & 31, w = tid >> 5;
    const int jt = blockIdx.x >> 2, bt = blockIdx.x & 3;

    // ---- W prologue: rows jt*32..+31 fp32 -> bf16 hi/lo SMEM [j][k] ----
    {
        const int r = tid >> 3, kq = tid & 7;
        const float* wr = Whh + (size_t)(jt * 32 + r) * HIDDEN;
        unsigned char* pH = dynsm + OFF_WH + r * KROWB + kq * 8;
        unsigned char* pL = dynsm + OFF_WL + r * KROWB + kq * 8;
#pragma unroll 8
        for (int i = 0; i < 32; ++i) {
            float4 v = __ldg((const float4*)(wr + kq * 4 + i * 32));
            uint2 h, lo;
            cvt4(v, h, lo);
            *(uint2*)(pH + i * 64) = h;
            *(uint2*)(pL + i * 64) = lo;
        }
    }
    __syncthreads();

    // ---- preload B fragments (W) into registers: warp w = K slice w*128 ----
    const int rowB = (l & 7) + ((l >= 16) ? 8 : 0);
    const int kBy = ((l & 8) ? 16 : 0);
    unsigned bfh[16][4], bfl[16][4];
#pragma unroll
    for (int kk = 0; kk < 8; ++kk) {
#pragma unroll
        for (int g = 0; g < 2; ++g) {
            const uint32_t o = (g * 16 + rowB) * KROWB + w * 256 + kk * 32 + kBy;
            LDSM_X4(bfh[kk * 2 + g], sbase + OFF_WH + o);
            LDSM_X4(bfl[kk * 2 + g], sbase + OFF_WL + o);
        }
    }

    // ---- A-frag lane addresses (XOR-16B swizzle on row bit3) ----
    const int rowA = (l & 7) + (l & 8);
    const int kAy = (l >> 4) * 16;
    const uint32_t aAH = sbase + OFF_AH + rowA * KROWB
                       + (kAy ^ ((rowA & 8) << 1)) + w * 256;
    const uint32_t aAL = aAH + (OFF_AL - OFF_AH);

    // ---- staging ids ----
    const int sb_ = tid >> 4, skq = tid & 15;
    const int sgoff = (bt * 16 + sb_) * HIDDEN;
    const uint32_t sAH = OFF_AH + sb_ * KROWB + ((skq * 8) ^ ((sb_ & 8) << 1));
    const uint32_t sAL = sAH + (OFF_AL - OFF_AH);

    // ---- reduce ids ----
    const int jj = tid & 31, brow = tid >> 5;

    unsigned expected = 0;
    int cur = 0;
    float lastv0 = 0.f, lastv1 = 0.f;

    for (int t = 0; t < SRC_LEN; ++t) {
        const size_t xb = (size_t)t * (BATCH * HIDDEN) + jt * 32 + jj;
        const float xv0 = __ldcg(g_xproj + xb + (size_t)(bt * 16 + brow) * HIDDEN);
        const float xv1 = __ldcg(g_xproj + xb + (size_t)(bt * 16 + brow + 8) * HIDDEN);

        // ---- stage h slice: packed u32 -> PRMT split -> bf16 planes ----
        const unsigned* gh = g_hx[cur] + sgoff;
#pragma unroll
        for (int i = 0; i < 16; ++i) {
            uint4 v = __ldcg((const uint4*)(gh + skq * 4 + i * 64));
            unsigned h01 = prmt(v.x, v.y, 0x5410u);
            unsigned h23 = prmt(v.z, v.w, 0x5410u);
            unsigned l01 = prmt(v.x, v.y, 0x7632u);
            unsigned l23 = prmt(v.z, v.w, 0x7632u);
            *(uint2*)(dynsm + sAH + i * 128) = make_uint2(h01, h23);
            *(uint2*)(dynsm + sAL + i * 128) = make_uint2(l01, l23);
        }
        __syncthreads();

        // ---- MMA: 8 k16 x (4 n-tiles x 3 products) ----
        float acc[4][4];
#pragma unroll
        for (int n = 0; n < 4; ++n) { acc[n][0]=0.f; acc[n][1]=0.f; acc[n][2]=0.f; acc[n][3]=0.f; }
#pragma unroll
        for (int kk = 0; kk < 8; ++kk) {
            unsigned ah[4], al[4];
            LDSM_X4(ah, aAH + kk * 32);
            LDSM_X4(al, aAL + kk * 32);
#pragma unroll
            for (int g = 0; g < 2; ++g) {
                const int ix = kk * 2 + g;
                mma16816(acc[2*g],   ah, bfh[ix][0], bfh[ix][1]);
                mma16816(acc[2*g+1], ah, bfh[ix][2], bfh[ix][3]);
                mma16816(acc[2*g],   ah, bfl[ix][0], bfl[ix][1]);
                mma16816(acc[2*g+1], ah, bfl[ix][2], bfl[ix][3]);
                mma16816(acc[2*g],   al, bfh[ix][0], bfh[ix][1]);
                mma16816(acc[2*g+1], al, bfh[ix][2], bfh[ix][3]);
            }
        }

        // ---- spill partials: red[w][r][c], row stride 40 floats ----
        {
            const int r0 = l >> 2;
            float* rp = red + (w * 16 + r0) * 40;
#pragma unroll
            for (int nt = 0; nt < 4; ++nt) {
                const int c = nt * 8 + (l & 3) * 2;
                *(float2*)(rp + c)          = make_float2(acc[nt][0], acc[nt][1]);
                *(float2*)(rp + 8 * 40 + c) = make_float2(acc[nt][2], acc[nt][3]);
            }
        }
        __syncthreads();

        // ---- reduce 8 warps, + xv, tanh, pack-split, store h_next [b][k] ----
        {
            float s0 = xv0, s1 = xv1;
#pragma unroll
            for (int wq = 0; wq < 8; ++wq) {
                s0 += red[(wq * 16 + brow) * 40 + jj];
                s1 += red[(wq * 16 + brow + 8) * 40 + jj];
            }
            lastv0 = tanhf(s0);
            lastv1 = tanhf(s1);
            unsigned* hn = g_hx[cur ^ 1];
            __stcg(hn + (size_t)(bt * 16 + brow)     * HIDDEN + jt * 32 + jj, packsplit(lastv0));
            __stcg(hn + (size_t)(bt * 16 + brow + 8) * HIDDEN + jt * 32 + jj, packsplit(lastv1));
        }

        // ---- grid-wide barrier (R12 proven form: fence + ATOMG + spin) ----
        expected += NBLK;
        __threadfence();
        __syncthreads();
        if (tid == 0) {
            atomicAdd(&g_bar, 1u);
            while (*(volatile unsigned*)&g_bar < expected) { }
        }
        __syncthreads();
        cur ^= 1;
    }
    out[(size_t)(bt * 16 + brow)     * HIDDEN + jt * 32 + jj] = lastv0;
    out[(size_t)(bt * 16 + brow + 8) * HIDDEN + jt * 32 + jj] = lastv1;
}

// ---------------------------------------------------------------------------
extern "C" void kernel_launch(void* const* d_in, const int* in_sizes, int n_in,
                              void* d_out, int out_size)
{
    const int*   src = (const int*)  d_in[0];
    const float* emb = (const float*)d_in[1];
    const float* Wxh = (const float*)d_in[2];
    const float* bxh = (const float*)d_in[3];
    const float* Whh = (const float*)d_in[4];
    float* out = (float*)d_out;

    static int attr_set = 0;
    if (!attr_set) {
        cudaFuncSetAttribute(rnn_scan_kernel,
                             cudaFuncAttributeMaxDynamicSharedMemorySize, SCAN_SMEM);
        attr_set = 1;
    }

    init_kernel<<<256, 256>>>();
    probe_kernel<<<1, 32>>>();       // ncu alignment: capture -> rnn_scan_kernel
    xproj_kernel<<<dim3(8, 256), 256>>>(src, emb, Wxh, bxh);
    rnn_scan_kernel<<<NBLK, 256, SCAN_SMEM>>>(Whh, out);
}